// round 2
// baseline (speedup 1.0000x reference)
#include <cuda_runtime.h>
#include <stdint.h>

#define BB 4
#define NN 50000
#define FF 128
#define EE 800000
#define MROWS (BB * NN)                 // 200000 projected rows
#define NCHUNK ((NN + 255) / 256)       // 196 scan chunks

// ---- device scratch (no allocations allowed in kernel_launch) ----
__device__ float g_h[(size_t)MROWS * FF];   // projected features, 102.4 MB
__device__ int   g_deg[NN];
__device__ int   g_excl[NN];
__device__ int   g_blksum[NCHUNK];
__device__ int   g_blkoff[NCHUNK];
__device__ int   g_rowptr[NN + 1];
__device__ int   g_cursor[NN];
__device__ int   g_col[EE];
__device__ float g_val[EE];

// ---------------- CSR build ----------------

__global__ void k_zero_deg() {
    int i = blockIdx.x * 256 + threadIdx.x;
    if (i < NN) g_deg[i] = 0;
}

__global__ void k_hist(const int* __restrict__ er, int E) {
    int e = blockIdx.x * 256 + threadIdx.x;
    if (e < E) atomicAdd(&g_deg[er[e]], 1);
}

// per-chunk exclusive scan (256 elems/block)
__global__ void k_scan1() {
    __shared__ int s[256];
    int b = blockIdx.x, t = threadIdx.x;
    int i = b * 256 + t;
    int v = (i < NN) ? g_deg[i] : 0;
    s[t] = v;
    __syncthreads();
#pragma unroll
    for (int o = 1; o < 256; o <<= 1) {
        int x = (t >= o) ? s[t - o] : 0;
        __syncthreads();
        s[t] += x;
        __syncthreads();
    }
    if (i < NN) g_excl[i] = s[t] - v;
    if (t == 255) g_blksum[b] = s[255];
}

// scan of chunk totals (NCHUNK <= 256)
__global__ void k_scan2() {
    __shared__ int s[256];
    int t = threadIdx.x;
    int v = (t < NCHUNK) ? g_blksum[t] : 0;
    s[t] = v;
    __syncthreads();
#pragma unroll
    for (int o = 1; o < 256; o <<= 1) {
        int x = (t >= o) ? s[t - o] : 0;
        __syncthreads();
        s[t] += x;
        __syncthreads();
    }
    if (t < NCHUNK) g_blkoff[t] = s[t] - v;
}

__global__ void k_scan3(int E) {
    int b = blockIdx.x, t = threadIdx.x;
    int i = b * 256 + t;
    if (i < NN) {
        int p = g_excl[i] + g_blkoff[b];
        g_rowptr[i] = p;
        g_cursor[i] = p;
    }
    if (i == 0) g_rowptr[NN] = E;
}

__global__ void k_scatter(const int* __restrict__ er,
                          const int* __restrict__ ec,
                          const float* __restrict__ ev, int E) {
    int e = blockIdx.x * 256 + threadIdx.x;
    if (e < E) {
        int r = er[e];
        int p = atomicAdd(&g_cursor[r], 1);
        g_col[p] = ec[e];
        g_val[p] = ev[e];
    }
}

// ---------------- GEMM: h = x @ W^T ----------------
// BM=128, BN=128(full), BK=16, 256 threads, 8x8 microtile.

__global__ __launch_bounds__(256) void k_gemm(const float* __restrict__ x,
                                              const float* __restrict__ W) {
    __shared__ float As[16][128];  // As[k][m] = x[row][k]
    __shared__ float Bs[16][128];  // Bs[k][o] = W[o][k]
    int tid = threadIdx.x;
    int tx = tid & 15;   // output-feature group
    int ty = tid >> 4;   // row group
    int brow = blockIdx.x * 128;

    float acc[8][8];
#pragma unroll
    for (int i = 0; i < 8; i++)
#pragma unroll
        for (int j = 0; j < 8; j++) acc[i][j] = 0.f;

    for (int k0 = 0; k0 < 128; k0 += 16) {
#pragma unroll
        for (int it = 0; it < 2; it++) {
            int idx = tid + it * 256;       // 0..511
            int m = idx >> 2;               // 0..127
            int kq = (idx & 3) << 2;        // 0,4,8,12
            int grow = brow + m;
            float4 v = make_float4(0.f, 0.f, 0.f, 0.f);
            if (grow < MROWS)
                v = *(const float4*)(x + (size_t)grow * 128 + k0 + kq);
            As[kq + 0][m] = v.x; As[kq + 1][m] = v.y;
            As[kq + 2][m] = v.z; As[kq + 3][m] = v.w;
            float4 w = *(const float4*)(W + (size_t)m * 128 + k0 + kq);
            Bs[kq + 0][m] = w.x; Bs[kq + 1][m] = w.y;
            Bs[kq + 2][m] = w.z; Bs[kq + 3][m] = w.w;
        }
        __syncthreads();
#pragma unroll
        for (int k = 0; k < 16; k++) {
            float4 a0 = *(const float4*)&As[k][ty * 8];
            float4 a1 = *(const float4*)&As[k][ty * 8 + 4];
            float4 b0 = *(const float4*)&Bs[k][tx * 8];
            float4 b1 = *(const float4*)&Bs[k][tx * 8 + 4];
            float a[8] = {a0.x, a0.y, a0.z, a0.w, a1.x, a1.y, a1.z, a1.w};
            float b[8] = {b0.x, b0.y, b0.z, b0.w, b1.x, b1.y, b1.z, b1.w};
#pragma unroll
            for (int i = 0; i < 8; i++)
#pragma unroll
                for (int j = 0; j < 8; j++)
                    acc[i][j] = fmaf(a[i], b[j], acc[i][j]);
        }
        __syncthreads();
    }

#pragma unroll
    for (int i = 0; i < 8; i++) {
        int grow = brow + ty * 8 + i;
        if (grow < MROWS) {
            float4 o0 = make_float4(acc[i][0], acc[i][1], acc[i][2], acc[i][3]);
            float4 o1 = make_float4(acc[i][4], acc[i][5], acc[i][6], acc[i][7]);
            *(float4*)(g_h + (size_t)grow * 128 + tx * 8) = o0;
            *(float4*)(g_h + (size_t)grow * 128 + tx * 8 + 4) = o1;
        }
    }
}

// ---------------- SpMM gather: out[b][n] = sum val * h[b][col] ----------------
// one 128-thread block per (node, batch); thread = feature. No atomics.

__global__ __launch_bounds__(128) void k_spmm(float* __restrict__ out) {
    int n = blockIdx.x;
    int b = blockIdx.y;
    int f = threadIdx.x;
    int s = g_rowptr[n];
    int e = g_rowptr[n + 1];
    const float* hb = g_h + (size_t)b * NN * FF;

    float acc = 0.f;
    int i = s;
    for (; i + 3 < e; i += 4) {
        int   c0 = g_col[i],     c1 = g_col[i + 1];
        int   c2 = g_col[i + 2], c3 = g_col[i + 3];
        float v0 = g_val[i],     v1 = g_val[i + 1];
        float v2 = g_val[i + 2], v3 = g_val[i + 3];
        float h0 = hb[(size_t)c0 * FF + f];
        float h1 = hb[(size_t)c1 * FF + f];
        float h2 = hb[(size_t)c2 * FF + f];
        float h3 = hb[(size_t)c3 * FF + f];
        acc = fmaf(v0, h0, acc);
        acc = fmaf(v1, h1, acc);
        acc = fmaf(v2, h2, acc);
        acc = fmaf(v3, h3, acc);
    }
    for (; i < e; i++)
        acc = fmaf(g_val[i], hb[(size_t)g_col[i] * FF + f], acc);

    out[((size_t)b * NN + n) * FF + f] = acc;
}

// ---------------- launch ----------------

extern "C" void kernel_launch(void* const* d_in, const int* in_sizes, int n_in,
                              void* d_out, int out_size) {
    const float* x  = (const float*)d_in[0];   // [B,N,F_in]
    const float* W  = (const float*)d_in[1];   // [F_out,F_in]
    const int*   er = (const int*)d_in[2];     // [E] int32 (JAX demotes int64)
    const int*   ec = (const int*)d_in[3];     // [E] int32
    const float* ev = (const float*)d_in[4];   // [E]
    float* out = (float*)d_out;
    int E = in_sizes[2];

    // CSR build (device-side, graph-capturable)
    k_zero_deg<<<(NN + 255) / 256, 256>>>();
    k_hist<<<(E + 255) / 256, 256>>>(er, E);
    k_scan1<<<NCHUNK, 256>>>();
    k_scan2<<<1, 256>>>();
    k_scan3<<<NCHUNK, 256>>>(E);
    k_scatter<<<(E + 255) / 256, 256>>>(er, ec, ev, E);

    // dense projection
    k_gemm<<<(MROWS + 127) / 128, 256>>>(x, W);

    // sparse aggregation
    dim3 sgrid(NN, BB);
    k_spmm<<<sgrid, 128>>>(out);
}

// round 3
// speedup vs baseline: 1.4621x; 1.4621x over previous
#include <cuda_runtime.h>
#include <stdint.h>

#define BB 4
#define NN 50000
#define FF 128
#define EE 800000
#define MROWS (BB * NN)                 // 200000 projected rows
#define NCHUNK ((NN + 255) / 256)       // 196 scan chunks

// ---- device scratch ----
__device__ float g_h[(size_t)MROWS * FF];   // projected features, 102.4 MB
__device__ int   g_deg[NN];
__device__ int   g_excl[NN];
__device__ int   g_blksum[NCHUNK];
__device__ int   g_blkoff[NCHUNK];
__device__ int   g_rowptr[NN + 1];
__device__ int   g_cursor[NN];
__device__ int   g_col[EE];
__device__ float g_val[EE];

// ---------------- CSR build ----------------

__global__ void k_zero_deg() {
    int i = blockIdx.x * 256 + threadIdx.x;
    if (i < NN) g_deg[i] = 0;
}

__global__ void k_hist(const int* __restrict__ er, int E) {
    int e = blockIdx.x * 256 + threadIdx.x;
    if (e < E) atomicAdd(&g_deg[er[e]], 1);
}

__global__ void k_scan1() {
    __shared__ int s[256];
    int b = blockIdx.x, t = threadIdx.x;
    int i = b * 256 + t;
    int v = (i < NN) ? g_deg[i] : 0;
    s[t] = v;
    __syncthreads();
#pragma unroll
    for (int o = 1; o < 256; o <<= 1) {
        int x = (t >= o) ? s[t - o] : 0;
        __syncthreads();
        s[t] += x;
        __syncthreads();
    }
    if (i < NN) g_excl[i] = s[t] - v;
    if (t == 255) g_blksum[b] = s[255];
}

__global__ void k_scan2() {
    __shared__ int s[256];
    int t = threadIdx.x;
    int v = (t < NCHUNK) ? g_blksum[t] : 0;
    s[t] = v;
    __syncthreads();
#pragma unroll
    for (int o = 1; o < 256; o <<= 1) {
        int x = (t >= o) ? s[t - o] : 0;
        __syncthreads();
        s[t] += x;
        __syncthreads();
    }
    if (t < NCHUNK) g_blkoff[t] = s[t] - v;
}

__global__ void k_scan3(int E) {
    int b = blockIdx.x, t = threadIdx.x;
    int i = b * 256 + t;
    if (i < NN) {
        int p = g_excl[i] + g_blkoff[b];
        g_rowptr[i] = p;
        g_cursor[i] = p;
    }
    if (i == 0) g_rowptr[NN] = E;
}

__global__ void k_scatter(const int* __restrict__ er,
                          const int* __restrict__ ec,
                          const float* __restrict__ ev, int E) {
    int e = blockIdx.x * 256 + threadIdx.x;
    if (e < E) {
        int r = er[e];
        int p = atomicAdd(&g_cursor[r], 1);
        g_col[p] = ec[e];
        g_val[p] = ev[e];
    }
}

// ---------------- GEMM: h = x @ W^T via tf32 mma.sync ----------------
// BM=128, BN=128, BK=16. 256 threads = 8 warps in 4(m) x 2(n) layout.
// Warp tile: 32(m) x 64(n) = 2 m16-tiles x 8 n8-tiles of m16n8k8.

__device__ __forceinline__ uint32_t f2tf32(float f) {
    uint32_t u;
    asm("cvt.rna.tf32.f32 %0, %1;" : "=r"(u) : "f"(f));
    return u;
}

#define LDA 132  // padded row length (bank-conflict avoidance)

__global__ __launch_bounds__(256) void k_gemm(const float* __restrict__ x,
                                              const float* __restrict__ W) {
    __shared__ uint32_t As[16][LDA];   // As[k][m] = tf32(x[brow+m][k0+k])
    __shared__ uint32_t Bs[16][LDA];   // Bs[k][o] = tf32(W[o][k0+k])

    int tid  = threadIdx.x;
    int lane = tid & 31;
    int wid  = tid >> 5;
    int warp_m = wid & 3;      // 0..3 -> 32 rows each
    int warp_n = wid >> 2;     // 0..1 -> 64 cols each
    int g  = lane >> 2;        // groupID 0..7
    int t4 = lane & 3;         // thread-in-group 0..3
    int brow = blockIdx.x * 128;

    float c[2][8][4];
#pragma unroll
    for (int mt = 0; mt < 2; mt++)
#pragma unroll
        for (int nt = 0; nt < 8; nt++)
#pragma unroll
            for (int r = 0; r < 4; r++) c[mt][nt][r] = 0.f;

    for (int k0 = 0; k0 < 128; k0 += 16) {
        // cooperative tile load: 128 rows x 16 k, as float4, transposed store
#pragma unroll
        for (int it = 0; it < 2; it++) {
            int idx = tid + it * 256;        // 0..511
            int m  = idx >> 2;               // 0..127
            int kq = (idx & 3) << 2;         // 0,4,8,12
            int grow = brow + m;
            float4 v = make_float4(0.f, 0.f, 0.f, 0.f);
            if (grow < MROWS)
                v = *(const float4*)(x + (size_t)grow * 128 + k0 + kq);
            As[kq + 0][m] = f2tf32(v.x);
            As[kq + 1][m] = f2tf32(v.y);
            As[kq + 2][m] = f2tf32(v.z);
            As[kq + 3][m] = f2tf32(v.w);
            float4 w = *(const float4*)(W + (size_t)m * 128 + k0 + kq);
            Bs[kq + 0][m] = f2tf32(w.x);
            Bs[kq + 1][m] = f2tf32(w.y);
            Bs[kq + 2][m] = f2tf32(w.z);
            Bs[kq + 3][m] = f2tf32(w.w);
        }
        __syncthreads();

#pragma unroll
        for (int ks = 0; ks < 2; ks++) {
            int kb = ks * 8;
            uint32_t a[2][4];
#pragma unroll
            for (int mt = 0; mt < 2; mt++) {
                int row = warp_m * 32 + mt * 16;
                a[mt][0] = As[kb + t4][row + g];
                a[mt][1] = As[kb + t4][row + g + 8];
                a[mt][2] = As[kb + t4 + 4][row + g];
                a[mt][3] = As[kb + t4 + 4][row + g + 8];
            }
            uint32_t b[8][2];
#pragma unroll
            for (int nt = 0; nt < 8; nt++) {
                int col = warp_n * 64 + nt * 8;
                b[nt][0] = Bs[kb + t4][col + g];
                b[nt][1] = Bs[kb + t4 + 4][col + g];
            }
#pragma unroll
            for (int mt = 0; mt < 2; mt++)
#pragma unroll
                for (int nt = 0; nt < 8; nt++) {
                    asm volatile(
                        "mma.sync.aligned.m16n8k8.row.col.f32.tf32.tf32.f32 "
                        "{%0,%1,%2,%3}, {%4,%5,%6,%7}, {%8,%9}, {%0,%1,%2,%3};"
                        : "+f"(c[mt][nt][0]), "+f"(c[mt][nt][1]),
                          "+f"(c[mt][nt][2]), "+f"(c[mt][nt][3])
                        : "r"(a[mt][0]), "r"(a[mt][1]), "r"(a[mt][2]), "r"(a[mt][3]),
                          "r"(b[nt][0]), "r"(b[nt][1]));
                }
        }
        __syncthreads();
    }

    // epilogue: c[mt][nt] frag -> rows (g, g+8), cols (2*t4, 2*t4+1)
#pragma unroll
    for (int mt = 0; mt < 2; mt++) {
        int row0 = brow + warp_m * 32 + mt * 16 + g;
        int row1 = row0 + 8;
#pragma unroll
        for (int nt = 0; nt < 8; nt++) {
            int col = warp_n * 64 + nt * 8 + t4 * 2;
            if (row0 < MROWS)
                *(float2*)(g_h + (size_t)row0 * 128 + col) =
                    make_float2(c[mt][nt][0], c[mt][nt][1]);
            if (row1 < MROWS)
                *(float2*)(g_h + (size_t)row1 * 128 + col) =
                    make_float2(c[mt][nt][2], c[mt][nt][3]);
        }
    }
}

// ---------------- SpMM gather: all 4 batches per block ----------------
// one 128-thread block per node; thread = feature; 4 batch accumulators.

__global__ __launch_bounds__(128) void k_spmm(float* __restrict__ out) {
    int n = blockIdx.x;
    int f = threadIdx.x;
    int s = g_rowptr[n];
    int e = g_rowptr[n + 1];

    const size_t BS = (size_t)NN * FF;
    float acc0 = 0.f, acc1 = 0.f, acc2 = 0.f, acc3 = 0.f;

    int i = s;
    for (; i + 1 < e; i += 2) {
        int   ca = g_col[i],     cb = g_col[i + 1];
        float va = g_val[i],     vb = g_val[i + 1];
        const float* pa = g_h + (size_t)ca * FF + f;
        const float* pb = g_h + (size_t)cb * FF + f;
        float a0 = pa[0],      b0 = pb[0];
        float a1 = pa[BS],     b1 = pb[BS];
        float a2 = pa[2 * BS], b2 = pb[2 * BS];
        float a3 = pa[3 * BS], b3 = pb[3 * BS];
        acc0 = fmaf(va, a0, acc0); acc0 = fmaf(vb, b0, acc0);
        acc1 = fmaf(va, a1, acc1); acc1 = fmaf(vb, b1, acc1);
        acc2 = fmaf(va, a2, acc2); acc2 = fmaf(vb, b2, acc2);
        acc3 = fmaf(va, a3, acc3); acc3 = fmaf(vb, b3, acc3);
    }
    if (i < e) {
        int   ca = g_col[i];
        float va = g_val[i];
        const float* pa = g_h + (size_t)ca * FF + f;
        acc0 = fmaf(va, pa[0], acc0);
        acc1 = fmaf(va, pa[BS], acc1);
        acc2 = fmaf(va, pa[2 * BS], acc2);
        acc3 = fmaf(va, pa[3 * BS], acc3);
    }

    size_t o = (size_t)n * FF + f;
    out[o]          = acc0;
    out[o + BS]     = acc1;
    out[o + 2 * BS] = acc2;
    out[o + 3 * BS] = acc3;
}

// ---------------- launch ----------------

extern "C" void kernel_launch(void* const* d_in, const int* in_sizes, int n_in,
                              void* d_out, int out_size) {
    const float* x  = (const float*)d_in[0];   // [B,N,F_in]
    const float* W  = (const float*)d_in[1];   // [F_out,F_in]
    const int*   er = (const int*)d_in[2];     // [E] int32
    const int*   ec = (const int*)d_in[3];     // [E] int32
    const float* ev = (const float*)d_in[4];   // [E]
    float* out = (float*)d_out;
    int E = in_sizes[2];

    // CSR build
    k_zero_deg<<<(NN + 255) / 256, 256>>>();
    k_hist<<<(E + 255) / 256, 256>>>(er, E);
    k_scan1<<<NCHUNK, 256>>>();
    k_scan2<<<1, 256>>>();
    k_scan3<<<NCHUNK, 256>>>(E);
    k_scatter<<<(E + 255) / 256, 256>>>(er, ec, ev, E);

    // dense projection (tf32 tensor cores)
    k_gemm<<<(MROWS + 127) / 128, 256>>>(x, W);

    // sparse aggregation (all batches per block)
    k_spmm<<<NN, 128>>>(out);
}

// round 4
// speedup vs baseline: 1.4892x; 1.0185x over previous
#include <cuda_runtime.h>
#include <stdint.h>

#define BB 4
#define NN 50000
#define FF 128
#define EE 800000
#define MROWS (BB * NN)                 // 200000 projected rows
#define NCHUNK ((NN + 255) / 256)       // 196 scan chunks

// ---- device scratch ----
__device__ float g_h[(size_t)MROWS * FF];   // projected features, 102.4 MB
__device__ int   g_deg[NN];
__device__ int   g_excl[NN];
__device__ int   g_blksum[NCHUNK];
__device__ int   g_blkoff[NCHUNK];
__device__ int   g_rowptr[NN + 1];
__device__ int   g_cursor[NN];
__device__ int   g_col[EE];
__device__ float g_val[EE];

// ---------------- CSR build ----------------

__global__ void k_zero_deg() {
    int i = blockIdx.x * 256 + threadIdx.x;
    if (i < NN) g_deg[i] = 0;
}

__global__ void k_hist(const int* __restrict__ er, int E) {
    int e = blockIdx.x * 256 + threadIdx.x;
    if (e < E) atomicAdd(&g_deg[er[e]], 1);
}

__global__ void k_scan1() {
    __shared__ int s[256];
    int b = blockIdx.x, t = threadIdx.x;
    int i = b * 256 + t;
    int v = (i < NN) ? g_deg[i] : 0;
    s[t] = v;
    __syncthreads();
#pragma unroll
    for (int o = 1; o < 256; o <<= 1) {
        int x = (t >= o) ? s[t - o] : 0;
        __syncthreads();
        s[t] += x;
        __syncthreads();
    }
    if (i < NN) g_excl[i] = s[t] - v;
    if (t == 255) g_blksum[b] = s[255];
}

__global__ void k_scan2() {
    __shared__ int s[256];
    int t = threadIdx.x;
    int v = (t < NCHUNK) ? g_blksum[t] : 0;
    s[t] = v;
    __syncthreads();
#pragma unroll
    for (int o = 1; o < 256; o <<= 1) {
        int x = (t >= o) ? s[t - o] : 0;
        __syncthreads();
        s[t] += x;
        __syncthreads();
    }
    if (t < NCHUNK) g_blkoff[t] = s[t] - v;
}

__global__ void k_scan3(int E) {
    int b = blockIdx.x, t = threadIdx.x;
    int i = b * 256 + t;
    if (i < NN) {
        int p = g_excl[i] + g_blkoff[b];
        g_rowptr[i] = p;
        g_cursor[i] = p;
    }
    if (i == 0) g_rowptr[NN] = E;
}

__global__ void k_scatter(const int* __restrict__ er,
                          const int* __restrict__ ec,
                          const float* __restrict__ ev, int E) {
    int e = blockIdx.x * 256 + threadIdx.x;
    if (e < E) {
        int r = er[e];
        int p = atomicAdd(&g_cursor[r], 1);
        g_col[p] = ec[e];
        g_val[p] = ev[e];
    }
}

// ---------------- GEMM: h = x @ W^T via tf32 mma.sync ----------------
// BM=128, BN=128, BK=16. 256 threads = 8 warps in 4(m) x 2(n) layout.
// Warp tile: 32(m) x 64(n) = 2 m16-tiles x 8 n8-tiles of m16n8k8.

__device__ __forceinline__ uint32_t f2tf32(float f) {
    uint32_t u;
    asm("cvt.rna.tf32.f32 %0, %1;" : "=r"(u) : "f"(f));
    return u;
}

#define LDA 132  // padded row length (bank-conflict avoidance)

__global__ __launch_bounds__(256) void k_gemm(const float* __restrict__ x,
                                              const float* __restrict__ W) {
    __shared__ uint32_t As[16][LDA];   // As[k][m] = tf32(x[brow+m][k0+k])
    __shared__ uint32_t Bs[16][LDA];   // Bs[k][o] = tf32(W[o][k0+k])

    int tid  = threadIdx.x;
    int lane = tid & 31;
    int wid  = tid >> 5;
    int warp_m = wid & 3;      // 0..3 -> 32 rows each
    int warp_n = wid >> 2;     // 0..1 -> 64 cols each
    int g  = lane >> 2;        // groupID 0..7
    int t4 = lane & 3;         // thread-in-group 0..3
    int brow = blockIdx.x * 128;

    float c[2][8][4];
#pragma unroll
    for (int mt = 0; mt < 2; mt++)
#pragma unroll
        for (int nt = 0; nt < 8; nt++)
#pragma unroll
            for (int r = 0; r < 4; r++) c[mt][nt][r] = 0.f;

    for (int k0 = 0; k0 < 128; k0 += 16) {
        // cooperative tile load: 128 rows x 16 k, as float4, transposed store
#pragma unroll
        for (int it = 0; it < 2; it++) {
            int idx = tid + it * 256;        // 0..511
            int m  = idx >> 2;               // 0..127
            int kq = (idx & 3) << 2;         // 0,4,8,12
            int grow = brow + m;
            float4 v = make_float4(0.f, 0.f, 0.f, 0.f);
            if (grow < MROWS)
                v = *(const float4*)(x + (size_t)grow * 128 + k0 + kq);
            As[kq + 0][m] = f2tf32(v.x);
            As[kq + 1][m] = f2tf32(v.y);
            As[kq + 2][m] = f2tf32(v.z);
            As[kq + 3][m] = f2tf32(v.w);
            float4 w = *(const float4*)(W + (size_t)m * 128 + k0 + kq);
            Bs[kq + 0][m] = f2tf32(w.x);
            Bs[kq + 1][m] = f2tf32(w.y);
            Bs[kq + 2][m] = f2tf32(w.z);
            Bs[kq + 3][m] = f2tf32(w.w);
        }
        __syncthreads();

#pragma unroll
        for (int ks = 0; ks < 2; ks++) {
            int kb = ks * 8;
            uint32_t a[2][4];
#pragma unroll
            for (int mt = 0; mt < 2; mt++) {
                int row = warp_m * 32 + mt * 16;
                a[mt][0] = As[kb + t4][row + g];
                a[mt][1] = As[kb + t4][row + g + 8];
                a[mt][2] = As[kb + t4 + 4][row + g];
                a[mt][3] = As[kb + t4 + 4][row + g + 8];
            }
            uint32_t b[8][2];
#pragma unroll
            for (int nt = 0; nt < 8; nt++) {
                int col = warp_n * 64 + nt * 8;
                b[nt][0] = Bs[kb + t4][col + g];
                b[nt][1] = Bs[kb + t4 + 4][col + g];
            }
#pragma unroll
            for (int mt = 0; mt < 2; mt++)
#pragma unroll
                for (int nt = 0; nt < 8; nt++) {
                    asm volatile(
                        "mma.sync.aligned.m16n8k8.row.col.f32.tf32.tf32.f32 "
                        "{%0,%1,%2,%3}, {%4,%5,%6,%7}, {%8,%9}, {%0,%1,%2,%3};"
                        : "+f"(c[mt][nt][0]), "+f"(c[mt][nt][1]),
                          "+f"(c[mt][nt][2]), "+f"(c[mt][nt][3])
                        : "r"(a[mt][0]), "r"(a[mt][1]), "r"(a[mt][2]), "r"(a[mt][3]),
                          "r"(b[nt][0]), "r"(b[nt][1]));
                }
        }
        __syncthreads();
    }

    // epilogue: c[mt][nt] frag -> rows (g, g+8), cols (2*t4, 2*t4+1)
#pragma unroll
    for (int mt = 0; mt < 2; mt++) {
        int row0 = brow + warp_m * 32 + mt * 16 + g;
        int row1 = row0 + 8;
#pragma unroll
        for (int nt = 0; nt < 8; nt++) {
            int col = warp_n * 64 + nt * 8 + t4 * 2;
            if (row0 < MROWS)
                *(float2*)(g_h + (size_t)row0 * 128 + col) =
                    make_float2(c[mt][nt][0], c[mt][nt][1]);
            if (row1 < MROWS)
                *(float2*)(g_h + (size_t)row1 * 128 + col) =
                    make_float2(c[mt][nt][2], c[mt][nt][3]);
        }
    }
}

// ---------------- SpMM gather: all 4 batches per block ----------------
// one 128-thread block per node; thread = feature; 4 batch accumulators.

__global__ __launch_bounds__(128) void k_spmm(float* __restrict__ out) {
    int n = blockIdx.x;
    int f = threadIdx.x;
    int s = g_rowptr[n];
    int e = g_rowptr[n + 1];

    const size_t BS = (size_t)NN * FF;
    float acc0 = 0.f, acc1 = 0.f, acc2 = 0.f, acc3 = 0.f;

    int i = s;
    for (; i + 1 < e; i += 2) {
        int   ca = g_col[i],     cb = g_col[i + 1];
        float va = g_val[i],     vb = g_val[i + 1];
        const float* pa = g_h + (size_t)ca * FF + f;
        const float* pb = g_h + (size_t)cb * FF + f;
        float a0 = pa[0],      b0 = pb[0];
        float a1 = pa[BS],     b1 = pb[BS];
        float a2 = pa[2 * BS], b2 = pb[2 * BS];
        float a3 = pa[3 * BS], b3 = pb[3 * BS];
        acc0 = fmaf(va, a0, acc0); acc0 = fmaf(vb, b0, acc0);
        acc1 = fmaf(va, a1, acc1); acc1 = fmaf(vb, b1, acc1);
        acc2 = fmaf(va, a2, acc2); acc2 = fmaf(vb, b2, acc2);
        acc3 = fmaf(va, a3, acc3); acc3 = fmaf(vb, b3, acc3);
    }
    if (i < e) {
        int   ca = g_col[i];
        float va = g_val[i];
        const float* pa = g_h + (size_t)ca * FF + f;
        acc0 = fmaf(va, pa[0], acc0);
        acc1 = fmaf(va, pa[BS], acc1);
        acc2 = fmaf(va, pa[2 * BS], acc2);
        acc3 = fmaf(va, pa[3 * BS], acc3);
    }

    size_t o = (size_t)n * FF + f;
    out[o]          = acc0;
    out[o + BS]     = acc1;
    out[o + 2 * BS] = acc2;
    out[o + 3 * BS] = acc3;
}

// ---------------- launch ----------------

extern "C" void kernel_launch(void* const* d_in, const int* in_sizes, int n_in,
                              void* d_out, int out_size) {
    const float* x  = (const float*)d_in[0];   // [B,N,F_in]
    const float* W  = (const float*)d_in[1];   // [F_out,F_in]
    const int*   er = (const int*)d_in[2];     // [E] int32
    const int*   ec = (const int*)d_in[3];     // [E] int32
    const float* ev = (const float*)d_in[4];   // [E]
    float* out = (float*)d_out;
    int E = in_sizes[2];

    // CSR build
    k_zero_deg<<<(NN + 255) / 256, 256>>>();
    k_hist<<<(E + 255) / 256, 256>>>(er, E);
    k_scan1<<<NCHUNK, 256>>>();
    k_scan2<<<1, 256>>>();
    k_scan3<<<NCHUNK, 256>>>(E);
    k_scatter<<<(E + 255) / 256, 256>>>(er, ec, ev, E);

    // dense projection (tf32 tensor cores)
    k_gemm<<<(MROWS + 127) / 128, 256>>>(x, W);

    // sparse aggregation (all batches per block)
    k_spmm<<<NN, 128>>>(out);
}

// round 5
// speedup vs baseline: 1.5512x; 1.0416x over previous
#include <cuda_runtime.h>
#include <stdint.h>

#define BB 4
#define NN 50000
#define FF 128
#define EE 800000
#define MROWS (BB * NN)                 // 200000 projected rows
#define NCHUNK ((NN + 255) / 256)       // 196 scan chunks

// ---- device scratch ----
__device__ float g_h[(size_t)MROWS * FF];   // projected features, 102.4 MB
__device__ int   g_deg[NN];
__device__ int   g_excl[NN];
__device__ int   g_blksum[NCHUNK];
__device__ int   g_blkoff[NCHUNK];
__device__ int   g_rowptr[NN + 1];
__device__ int   g_cursor[NN];
__device__ int   g_col[EE];
__device__ float g_val[EE];

// ---- streams/events for capture forking (created before harness checkpoints) ----
static cudaStream_t g_s1;
static cudaEvent_t  g_ev_root, g_ev_csr;
struct _StreamInit {
    _StreamInit() {
        cudaStreamCreateWithFlags(&g_s1, cudaStreamNonBlocking);
        cudaEventCreateWithFlags(&g_ev_root, cudaEventDisableTiming);
        cudaEventCreateWithFlags(&g_ev_csr,  cudaEventDisableTiming);
    }
};
static _StreamInit g_stream_init;

// ---------------- CSR build ----------------

__global__ void k_zero_deg() {
    int i = blockIdx.x * 256 + threadIdx.x;
    if (i < NN) g_deg[i] = 0;
}

__global__ void k_hist(const int* __restrict__ er, int E) {
    int e = blockIdx.x * 256 + threadIdx.x;
    if (e < E) atomicAdd(&g_deg[er[e]], 1);
}

__global__ void k_scan1() {
    __shared__ int s[256];
    int b = blockIdx.x, t = threadIdx.x;
    int i = b * 256 + t;
    int v = (i < NN) ? g_deg[i] : 0;
    s[t] = v;
    __syncthreads();
#pragma unroll
    for (int o = 1; o < 256; o <<= 1) {
        int x = (t >= o) ? s[t - o] : 0;
        __syncthreads();
        s[t] += x;
        __syncthreads();
    }
    if (i < NN) g_excl[i] = s[t] - v;
    if (t == 255) g_blksum[b] = s[255];
}

__global__ void k_scan2() {
    __shared__ int s[256];
    int t = threadIdx.x;
    int v = (t < NCHUNK) ? g_blksum[t] : 0;
    s[t] = v;
    __syncthreads();
#pragma unroll
    for (int o = 1; o < 256; o <<= 1) {
        int x = (t >= o) ? s[t - o] : 0;
        __syncthreads();
        s[t] += x;
        __syncthreads();
    }
    if (t < NCHUNK) g_blkoff[t] = s[t] - v;
}

__global__ void k_scan3(int E) {
    int b = blockIdx.x, t = threadIdx.x;
    int i = b * 256 + t;
    if (i < NN) {
        int p = g_excl[i] + g_blkoff[b];
        g_rowptr[i] = p;
        g_cursor[i] = p;
    }
    if (i == 0) g_rowptr[NN] = E;
}

__global__ void k_scatter(const int* __restrict__ er,
                          const int* __restrict__ ec,
                          const float* __restrict__ ev, int E) {
    int e = blockIdx.x * 256 + threadIdx.x;
    if (e < E) {
        int r = er[e];
        int p = atomicAdd(&g_cursor[r], 1);
        g_col[p] = ec[e];
        g_val[p] = ev[e];
    }
}

// ---------------- GEMM: h = x @ W^T via tf32 mma.sync ----------------
// BM=128, BN=128, BK=16. 256 threads = 8 warps in 4(m) x 2(n) layout.
// Warp tile: 32(m) x 64(n) = 2 m16-tiles x 8 n8-tiles of m16n8k8.

__device__ __forceinline__ uint32_t f2tf32(float f) {
    uint32_t u;
    asm("cvt.rna.tf32.f32 %0, %1;" : "=r"(u) : "f"(f));
    return u;
}

#define LDA 132  // padded row length (bank-conflict avoidance)

__global__ __launch_bounds__(256) void k_gemm(const float* __restrict__ x,
                                              const float* __restrict__ W) {
    __shared__ uint32_t As[16][LDA];   // As[k][m] = tf32(x[brow+m][k0+k])
    __shared__ uint32_t Bs[16][LDA];   // Bs[k][o] = tf32(W[o][k0+k])

    int tid  = threadIdx.x;
    int lane = tid & 31;
    int wid  = tid >> 5;
    int warp_m = wid & 3;      // 0..3 -> 32 rows each
    int warp_n = wid >> 2;     // 0..1 -> 64 cols each
    int g  = lane >> 2;        // groupID 0..7
    int t4 = lane & 3;         // thread-in-group 0..3
    int brow = blockIdx.x * 128;

    float c[2][8][4];
#pragma unroll
    for (int mt = 0; mt < 2; mt++)
#pragma unroll
        for (int nt = 0; nt < 8; nt++)
#pragma unroll
            for (int r = 0; r < 4; r++) c[mt][nt][r] = 0.f;

    for (int k0 = 0; k0 < 128; k0 += 16) {
#pragma unroll
        for (int it = 0; it < 2; it++) {
            int idx = tid + it * 256;        // 0..511
            int m  = idx >> 2;               // 0..127
            int kq = (idx & 3) << 2;         // 0,4,8,12
            int grow = brow + m;
            float4 v = make_float4(0.f, 0.f, 0.f, 0.f);
            if (grow < MROWS)
                v = *(const float4*)(x + (size_t)grow * 128 + k0 + kq);
            As[kq + 0][m] = f2tf32(v.x);
            As[kq + 1][m] = f2tf32(v.y);
            As[kq + 2][m] = f2tf32(v.z);
            As[kq + 3][m] = f2tf32(v.w);
            float4 w = *(const float4*)(W + (size_t)m * 128 + k0 + kq);
            Bs[kq + 0][m] = f2tf32(w.x);
            Bs[kq + 1][m] = f2tf32(w.y);
            Bs[kq + 2][m] = f2tf32(w.z);
            Bs[kq + 3][m] = f2tf32(w.w);
        }
        __syncthreads();

#pragma unroll
        for (int ks = 0; ks < 2; ks++) {
            int kb = ks * 8;
            uint32_t a[2][4];
#pragma unroll
            for (int mt = 0; mt < 2; mt++) {
                int row = warp_m * 32 + mt * 16;
                a[mt][0] = As[kb + t4][row + g];
                a[mt][1] = As[kb + t4][row + g + 8];
                a[mt][2] = As[kb + t4 + 4][row + g];
                a[mt][3] = As[kb + t4 + 4][row + g + 8];
            }
            uint32_t b[8][2];
#pragma unroll
            for (int nt = 0; nt < 8; nt++) {
                int col = warp_n * 64 + nt * 8;
                b[nt][0] = Bs[kb + t4][col + g];
                b[nt][1] = Bs[kb + t4 + 4][col + g];
            }
#pragma unroll
            for (int mt = 0; mt < 2; mt++)
#pragma unroll
                for (int nt = 0; nt < 8; nt++) {
                    asm volatile(
                        "mma.sync.aligned.m16n8k8.row.col.f32.tf32.tf32.f32 "
                        "{%0,%1,%2,%3}, {%4,%5,%6,%7}, {%8,%9}, {%0,%1,%2,%3};"
                        : "+f"(c[mt][nt][0]), "+f"(c[mt][nt][1]),
                          "+f"(c[mt][nt][2]), "+f"(c[mt][nt][3])
                        : "r"(a[mt][0]), "r"(a[mt][1]), "r"(a[mt][2]), "r"(a[mt][3]),
                          "r"(b[nt][0]), "r"(b[nt][1]));
                }
        }
        __syncthreads();
    }

#pragma unroll
    for (int mt = 0; mt < 2; mt++) {
        int row0 = brow + warp_m * 32 + mt * 16 + g;
        int row1 = row0 + 8;
#pragma unroll
        for (int nt = 0; nt < 8; nt++) {
            int col = warp_n * 64 + nt * 8 + t4 * 2;
            if (row0 < MROWS)
                *(float2*)(g_h + (size_t)row0 * 128 + col) =
                    make_float2(c[mt][nt][0], c[mt][nt][1]);
            if (row1 < MROWS)
                *(float2*)(g_h + (size_t)row1 * 128 + col) =
                    make_float2(c[mt][nt][2], c[mt][nt][3]);
        }
    }
}

// ---------------- SpMM gather: all 4 batches per block ----------------
// one 128-thread block per node; thread = feature; 4 batch accumulators.
// Unrolled 4 edges -> 16 independent L2 gathers in flight per thread.

__global__ __launch_bounds__(128) void k_spmm(float* __restrict__ out) {
    int n = blockIdx.x;
    int f = threadIdx.x;
    int s = g_rowptr[n];
    int e = g_rowptr[n + 1];

    const size_t BS = (size_t)NN * FF;
    float acc0 = 0.f, acc1 = 0.f, acc2 = 0.f, acc3 = 0.f;

    int i = s;
    for (; i + 3 < e; i += 4) {
        int   c0 = g_col[i],     c1 = g_col[i + 1];
        int   c2 = g_col[i + 2], c3 = g_col[i + 3];
        float v0 = g_val[i],     v1 = g_val[i + 1];
        float v2 = g_val[i + 2], v3 = g_val[i + 3];
        const float* p0 = g_h + (size_t)c0 * FF + f;
        const float* p1 = g_h + (size_t)c1 * FF + f;
        const float* p2 = g_h + (size_t)c2 * FF + f;
        const float* p3 = g_h + (size_t)c3 * FF + f;
        float h00 = p0[0],      h10 = p1[0],      h20 = p2[0],      h30 = p3[0];
        float h01 = p0[BS],     h11 = p1[BS],     h21 = p2[BS],     h31 = p3[BS];
        float h02 = p0[2 * BS], h12 = p1[2 * BS], h22 = p2[2 * BS], h32 = p3[2 * BS];
        float h03 = p0[3 * BS], h13 = p1[3 * BS], h23 = p2[3 * BS], h33 = p3[3 * BS];
        acc0 = fmaf(v0, h00, acc0); acc0 = fmaf(v1, h10, acc0);
        acc0 = fmaf(v2, h20, acc0); acc0 = fmaf(v3, h30, acc0);
        acc1 = fmaf(v0, h01, acc1); acc1 = fmaf(v1, h11, acc1);
        acc1 = fmaf(v2, h21, acc1); acc1 = fmaf(v3, h31, acc1);
        acc2 = fmaf(v0, h02, acc2); acc2 = fmaf(v1, h12, acc2);
        acc2 = fmaf(v2, h22, acc2); acc2 = fmaf(v3, h32, acc2);
        acc3 = fmaf(v0, h03, acc3); acc3 = fmaf(v1, h13, acc3);
        acc3 = fmaf(v2, h23, acc3); acc3 = fmaf(v3, h33, acc3);
    }
    for (; i < e; i++) {
        int   ca = g_col[i];
        float va = g_val[i];
        const float* pa = g_h + (size_t)ca * FF + f;
        acc0 = fmaf(va, pa[0], acc0);
        acc1 = fmaf(va, pa[BS], acc1);
        acc2 = fmaf(va, pa[2 * BS], acc2);
        acc3 = fmaf(va, pa[3 * BS], acc3);
    }

    size_t o = (size_t)n * FF + f;
    out[o]          = acc0;
    out[o + BS]     = acc1;
    out[o + 2 * BS] = acc2;
    out[o + 3 * BS] = acc3;
}

// ---------------- launch ----------------

extern "C" void kernel_launch(void* const* d_in, const int* in_sizes, int n_in,
                              void* d_out, int out_size) {
    const float* x  = (const float*)d_in[0];   // [B,N,F_in]
    const float* W  = (const float*)d_in[1];   // [F_out,F_in]
    const int*   er = (const int*)d_in[2];     // [E] int32
    const int*   ec = (const int*)d_in[3];     // [E] int32
    const float* ev = (const float*)d_in[4];   // [E]
    float* out = (float*)d_out;
    int E = in_sizes[2];

    // Fork: CSR build on side stream s1, GEMM on main stream (independent work).
    cudaEventRecord(g_ev_root, 0);
    cudaStreamWaitEvent(g_s1, g_ev_root, 0);

    // CSR build (stream s1)
    k_zero_deg<<<(NN + 255) / 256, 256, 0, g_s1>>>();
    k_hist<<<(E + 255) / 256, 256, 0, g_s1>>>(er, E);
    k_scan1<<<NCHUNK, 256, 0, g_s1>>>();
    k_scan2<<<1, 256, 0, g_s1>>>();
    k_scan3<<<NCHUNK, 256, 0, g_s1>>>(E);
    k_scatter<<<(E + 255) / 256, 256, 0, g_s1>>>(er, ec, ev, E);
    cudaEventRecord(g_ev_csr, g_s1);

    // dense projection (tf32 tensor cores, main stream, concurrent with CSR)
    k_gemm<<<(MROWS + 127) / 128, 256>>>(x, W);

    // join: SpMM needs both g_h (GEMM) and CSR arrays
    cudaStreamWaitEvent(0, g_ev_csr, 0);
    k_spmm<<<NN, 128>>>(out);
}

// round 6
// speedup vs baseline: 2.1190x; 1.3660x over previous
#include <cuda_runtime.h>
#include <cuda_fp16.h>
#include <stdint.h>

#define BB 4
#define NN 50000
#define FF 128
#define EE 800000
#define MROWS (BB * NN)                 // 200000 projected rows
#define NCHUNK ((NN + 255) / 256)       // 196 scan chunks

// ---- device scratch ----
__device__ __half g_h[(size_t)MROWS * FF];  // projected features, fp16, 51.2 MB
__device__ int   g_deg[NN];
__device__ int   g_excl[NN];
__device__ int   g_blksum[NCHUNK];
__device__ int   g_blkoff[NCHUNK];
__device__ int   g_rowptr[NN + 1];
__device__ int   g_cursor[NN];
__device__ int   g_col[EE];
__device__ float g_val[EE];

// ---- streams/events for capture forking ----
static cudaStream_t g_s1;
static cudaEvent_t  g_ev_root, g_ev_csr;
struct _StreamInit {
    _StreamInit() {
        cudaStreamCreateWithFlags(&g_s1, cudaStreamNonBlocking);
        cudaEventCreateWithFlags(&g_ev_root, cudaEventDisableTiming);
        cudaEventCreateWithFlags(&g_ev_csr,  cudaEventDisableTiming);
    }
};
static _StreamInit g_stream_init;

// ---------------- CSR build ----------------

__global__ void k_zero_deg() {
    int i = blockIdx.x * 256 + threadIdx.x;
    if (i < NN) g_deg[i] = 0;
}

__global__ void k_hist(const int* __restrict__ er, int E) {
    int e = blockIdx.x * 256 + threadIdx.x;
    if (e < E) atomicAdd(&g_deg[er[e]], 1);
}

__global__ void k_scan1() {
    __shared__ int s[256];
    int b = blockIdx.x, t = threadIdx.x;
    int i = b * 256 + t;
    int v = (i < NN) ? g_deg[i] : 0;
    s[t] = v;
    __syncthreads();
#pragma unroll
    for (int o = 1; o < 256; o <<= 1) {
        int x = (t >= o) ? s[t - o] : 0;
        __syncthreads();
        s[t] += x;
        __syncthreads();
    }
    if (i < NN) g_excl[i] = s[t] - v;
    if (t == 255) g_blksum[b] = s[255];
}

__global__ void k_scan2() {
    __shared__ int s[256];
    int t = threadIdx.x;
    int v = (t < NCHUNK) ? g_blksum[t] : 0;
    s[t] = v;
    __syncthreads();
#pragma unroll
    for (int o = 1; o < 256; o <<= 1) {
        int x = (t >= o) ? s[t - o] : 0;
        __syncthreads();
        s[t] += x;
        __syncthreads();
    }
    if (t < NCHUNK) g_blkoff[t] = s[t] - v;
}

__global__ void k_scan3(int E) {
    int b = blockIdx.x, t = threadIdx.x;
    int i = b * 256 + t;
    if (i < NN) {
        int p = g_excl[i] + g_blkoff[b];
        g_rowptr[i] = p;
        g_cursor[i] = p;
    }
    if (i == 0) g_rowptr[NN] = E;
}

__global__ void k_scatter(const int* __restrict__ er,
                          const int* __restrict__ ec,
                          const float* __restrict__ ev, int E) {
    int e = blockIdx.x * 256 + threadIdx.x;
    if (e < E) {
        int r = er[e];
        int p = atomicAdd(&g_cursor[r], 1);
        g_col[p] = ec[e];
        g_val[p] = ev[e];
    }
}

// ---------------- GEMM: h = x @ W^T via tf32 mma.sync, fp16 epilogue ----------------

__device__ __forceinline__ uint32_t f2tf32(float f) {
    uint32_t u;
    asm("cvt.rna.tf32.f32 %0, %1;" : "=r"(u) : "f"(f));
    return u;
}

#define LDA 132  // padded row length (bank-conflict avoidance)

__global__ __launch_bounds__(256) void k_gemm(const float* __restrict__ x,
                                              const float* __restrict__ W) {
    __shared__ uint32_t As[16][LDA];   // As[k][m] = tf32(x[brow+m][k0+k])
    __shared__ uint32_t Bs[16][LDA];   // Bs[k][o] = tf32(W[o][k0+k])

    int tid  = threadIdx.x;
    int lane = tid & 31;
    int wid  = tid >> 5;
    int warp_m = wid & 3;      // 0..3 -> 32 rows each
    int warp_n = wid >> 2;     // 0..1 -> 64 cols each
    int g  = lane >> 2;        // groupID 0..7
    int t4 = lane & 3;         // thread-in-group 0..3
    int brow = blockIdx.x * 128;

    float c[2][8][4];
#pragma unroll
    for (int mt = 0; mt < 2; mt++)
#pragma unroll
        for (int nt = 0; nt < 8; nt++)
#pragma unroll
            for (int r = 0; r < 4; r++) c[mt][nt][r] = 0.f;

    for (int k0 = 0; k0 < 128; k0 += 16) {
#pragma unroll
        for (int it = 0; it < 2; it++) {
            int idx = tid + it * 256;        // 0..511
            int m  = idx >> 2;               // 0..127
            int kq = (idx & 3) << 2;         // 0,4,8,12
            int grow = brow + m;
            float4 v = make_float4(0.f, 0.f, 0.f, 0.f);
            if (grow < MROWS)
                v = *(const float4*)(x + (size_t)grow * 128 + k0 + kq);
            As[kq + 0][m] = f2tf32(v.x);
            As[kq + 1][m] = f2tf32(v.y);
            As[kq + 2][m] = f2tf32(v.z);
            As[kq + 3][m] = f2tf32(v.w);
            float4 w = *(const float4*)(W + (size_t)m * 128 + k0 + kq);
            Bs[kq + 0][m] = f2tf32(w.x);
            Bs[kq + 1][m] = f2tf32(w.y);
            Bs[kq + 2][m] = f2tf32(w.z);
            Bs[kq + 3][m] = f2tf32(w.w);
        }
        __syncthreads();

#pragma unroll
        for (int ks = 0; ks < 2; ks++) {
            int kb = ks * 8;
            uint32_t a[2][4];
#pragma unroll
            for (int mt = 0; mt < 2; mt++) {
                int row = warp_m * 32 + mt * 16;
                a[mt][0] = As[kb + t4][row + g];
                a[mt][1] = As[kb + t4][row + g + 8];
                a[mt][2] = As[kb + t4 + 4][row + g];
                a[mt][3] = As[kb + t4 + 4][row + g + 8];
            }
            uint32_t b[8][2];
#pragma unroll
            for (int nt = 0; nt < 8; nt++) {
                int col = warp_n * 64 + nt * 8;
                b[nt][0] = Bs[kb + t4][col + g];
                b[nt][1] = Bs[kb + t4 + 4][col + g];
            }
#pragma unroll
            for (int mt = 0; mt < 2; mt++)
#pragma unroll
                for (int nt = 0; nt < 8; nt++) {
                    asm volatile(
                        "mma.sync.aligned.m16n8k8.row.col.f32.tf32.tf32.f32 "
                        "{%0,%1,%2,%3}, {%4,%5,%6,%7}, {%8,%9}, {%0,%1,%2,%3};"
                        : "+f"(c[mt][nt][0]), "+f"(c[mt][nt][1]),
                          "+f"(c[mt][nt][2]), "+f"(c[mt][nt][3])
                        : "r"(a[mt][0]), "r"(a[mt][1]), "r"(a[mt][2]), "r"(a[mt][3]),
                          "r"(b[nt][0]), "r"(b[nt][1]));
                }
        }
        __syncthreads();
    }

    // epilogue: frag rows (g, g+8), cols (2*t4, 2*t4+1) -> half2 stores
#pragma unroll
    for (int mt = 0; mt < 2; mt++) {
        int row0 = brow + warp_m * 32 + mt * 16 + g;
        int row1 = row0 + 8;
#pragma unroll
        for (int nt = 0; nt < 8; nt++) {
            int col = warp_n * 64 + nt * 8 + t4 * 2;
            if (row0 < MROWS)
                *(__half2*)(g_h + (size_t)row0 * 128 + col) =
                    __floats2half2_rn(c[mt][nt][0], c[mt][nt][1]);
            if (row1 < MROWS)
                *(__half2*)(g_h + (size_t)row1 * 128 + col) =
                    __floats2half2_rn(c[mt][nt][2], c[mt][nt][3]);
        }
    }
}

// ---------------- SpMM gather (fp16 h, fp32 accumulate) ----------------
// One 128-thread block per node. Thread layout: tid>>6 selects batch pair
// (0,1) or (2,3); tid&63 selects a feature pair (half2). fp32 accumulators.

__global__ __launch_bounds__(128) void k_spmm(float* __restrict__ out) {
    int n   = blockIdx.x;
    int tid = threadIdx.x;
    int hb  = tid >> 6;            // 0 -> batches 0,1 ; 1 -> batches 2,3
    int fo  = tid & 63;            // half2 index within row (features 2fo, 2fo+1)
    int b0  = hb * 2, b1 = b0 + 1;
    int s = g_rowptr[n];
    int e = g_rowptr[n + 1];

    const __half2* hp0 = (const __half2*)g_h + (size_t)b0 * NN * 64 + fo;
    const __half2* hp1 = (const __half2*)g_h + (size_t)b1 * NN * 64 + fo;

    float2 acc0 = make_float2(0.f, 0.f);
    float2 acc1 = make_float2(0.f, 0.f);

    int i = s;
    for (; i + 3 < e; i += 4) {
        int   c0 = g_col[i],     c1 = g_col[i + 1];
        int   c2 = g_col[i + 2], c3 = g_col[i + 3];
        float v0 = g_val[i],     v1 = g_val[i + 1];
        float v2 = g_val[i + 2], v3 = g_val[i + 3];
        float2 a0 = __half22float2(hp0[(size_t)c0 * 64]);
        float2 a1 = __half22float2(hp0[(size_t)c1 * 64]);
        float2 a2 = __half22float2(hp0[(size_t)c2 * 64]);
        float2 a3 = __half22float2(hp0[(size_t)c3 * 64]);
        float2 d0 = __half22float2(hp1[(size_t)c0 * 64]);
        float2 d1 = __half22float2(hp1[(size_t)c1 * 64]);
        float2 d2 = __half22float2(hp1[(size_t)c2 * 64]);
        float2 d3 = __half22float2(hp1[(size_t)c3 * 64]);
        acc0.x = fmaf(v0, a0.x, acc0.x); acc0.y = fmaf(v0, a0.y, acc0.y);
        acc0.x = fmaf(v1, a1.x, acc0.x); acc0.y = fmaf(v1, a1.y, acc0.y);
        acc0.x = fmaf(v2, a2.x, acc0.x); acc0.y = fmaf(v2, a2.y, acc0.y);
        acc0.x = fmaf(v3, a3.x, acc0.x); acc0.y = fmaf(v3, a3.y, acc0.y);
        acc1.x = fmaf(v0, d0.x, acc1.x); acc1.y = fmaf(v0, d0.y, acc1.y);
        acc1.x = fmaf(v1, d1.x, acc1.x); acc1.y = fmaf(v1, d1.y, acc1.y);
        acc1.x = fmaf(v2, d2.x, acc1.x); acc1.y = fmaf(v2, d2.y, acc1.y);
        acc1.x = fmaf(v3, d3.x, acc1.x); acc1.y = fmaf(v3, d3.y, acc1.y);
    }
    for (; i < e; i++) {
        int   ca = g_col[i];
        float va = g_val[i];
        float2 a = __half22float2(hp0[(size_t)ca * 64]);
        float2 d = __half22float2(hp1[(size_t)ca * 64]);
        acc0.x = fmaf(va, a.x, acc0.x); acc0.y = fmaf(va, a.y, acc0.y);
        acc1.x = fmaf(va, d.x, acc1.x); acc1.y = fmaf(va, d.y, acc1.y);
    }

    *(float2*)(out + ((size_t)b0 * NN + n) * FF + fo * 2) = acc0;
    *(float2*)(out + ((size_t)b1 * NN + n) * FF + fo * 2) = acc1;
}

// ---------------- launch ----------------

extern "C" void kernel_launch(void* const* d_in, const int* in_sizes, int n_in,
                              void* d_out, int out_size) {
    const float* x  = (const float*)d_in[0];   // [B,N,F_in]
    const float* W  = (const float*)d_in[1];   // [F_out,F_in]
    const int*   er = (const int*)d_in[2];     // [E] int32
    const int*   ec = (const int*)d_in[3];     // [E] int32
    const float* ev = (const float*)d_in[4];   // [E]
    float* out = (float*)d_out;
    int E = in_sizes[2];

    // Fork: CSR build on side stream s1, GEMM on main stream.
    cudaEventRecord(g_ev_root, 0);
    cudaStreamWaitEvent(g_s1, g_ev_root, 0);

    // CSR build (stream s1)
    k_zero_deg<<<(NN + 255) / 256, 256, 0, g_s1>>>();
    k_hist<<<(E + 255) / 256, 256, 0, g_s1>>>(er, E);
    k_scan1<<<NCHUNK, 256, 0, g_s1>>>();
    k_scan2<<<1, 256, 0, g_s1>>>();
    k_scan3<<<NCHUNK, 256, 0, g_s1>>>(E);
    k_scatter<<<(E + 255) / 256, 256, 0, g_s1>>>(er, ec, ev, E);
    cudaEventRecord(g_ev_csr, g_s1);

    // dense projection (tf32 tensor cores, fp16 output, main stream)
    k_gemm<<<(MROWS + 127) / 128, 256>>>(x, W);

    // join: SpMM needs both g_h (GEMM) and CSR arrays
    cudaStreamWaitEvent(0, g_ev_csr, 0);
    k_spmm<<<NN, 128>>>(out);
}

// round 7
// speedup vs baseline: 2.1547x; 1.0168x over previous
#include <cuda_runtime.h>
#include <cuda_fp16.h>
#include <stdint.h>

#define BB 4
#define NN 50000
#define FF 128
#define EE 800000
#define MROWS (BB * NN)                 // 200000 projected rows
#define NCHUNK ((NN + 255) / 256)       // 196 scan chunks

// ---- device scratch ----
__device__ __half g_h[(size_t)MROWS * FF];  // projected features, fp16, 51.2 MB
__device__ int   g_deg[NN];
__device__ int   g_excl[NN];
__device__ int   g_blksum[NCHUNK];
__device__ int   g_blkoff[NCHUNK];
__device__ int   g_rowptr[NN + 1];
__device__ int   g_cursor[NN];
__device__ int   g_col[EE];
__device__ float g_val[EE];

// ---- streams/events for capture forking ----
static cudaStream_t g_s1;
static cudaEvent_t  g_ev_root, g_ev_csr;
struct _StreamInit {
    _StreamInit() {
        cudaStreamCreateWithFlags(&g_s1, cudaStreamNonBlocking);
        cudaEventCreateWithFlags(&g_ev_root, cudaEventDisableTiming);
        cudaEventCreateWithFlags(&g_ev_csr,  cudaEventDisableTiming);
    }
};
static _StreamInit g_stream_init;

// ---------------- CSR build ----------------

__global__ void k_zero_deg() {
    int i = blockIdx.x * 256 + threadIdx.x;
    if (i < NN) g_deg[i] = 0;
}

__global__ void k_hist(const int* __restrict__ er, int E) {
    int e = blockIdx.x * 256 + threadIdx.x;
    if (e < E) atomicAdd(&g_deg[er[e]], 1);
}

__global__ void k_scan1() {
    __shared__ int s[256];
    int b = blockIdx.x, t = threadIdx.x;
    int i = b * 256 + t;
    int v = (i < NN) ? g_deg[i] : 0;
    s[t] = v;
    __syncthreads();
#pragma unroll
    for (int o = 1; o < 256; o <<= 1) {
        int x = (t >= o) ? s[t - o] : 0;
        __syncthreads();
        s[t] += x;
        __syncthreads();
    }
    if (i < NN) g_excl[i] = s[t] - v;
    if (t == 255) g_blksum[b] = s[255];
}

__global__ void k_scan2() {
    __shared__ int s[256];
    int t = threadIdx.x;
    int v = (t < NCHUNK) ? g_blksum[t] : 0;
    s[t] = v;
    __syncthreads();
#pragma unroll
    for (int o = 1; o < 256; o <<= 1) {
        int x = (t >= o) ? s[t - o] : 0;
        __syncthreads();
        s[t] += x;
        __syncthreads();
    }
    if (t < NCHUNK) g_blkoff[t] = s[t] - v;
}

__global__ void k_scan3(int E) {
    int b = blockIdx.x, t = threadIdx.x;
    int i = b * 256 + t;
    if (i < NN) {
        int p = g_excl[i] + g_blkoff[b];
        g_rowptr[i] = p;
        g_cursor[i] = p;
    }
    if (i == 0) g_rowptr[NN] = E;
}

__global__ void k_scatter(const int* __restrict__ er,
                          const int* __restrict__ ec,
                          const float* __restrict__ ev, int E) {
    int e = blockIdx.x * 256 + threadIdx.x;
    if (e < E) {
        int r = er[e];
        int p = atomicAdd(&g_cursor[r], 1);
        g_col[p] = ec[e];
        g_val[p] = ev[e];
    }
}

// ---------------- GEMM: h = x @ W^T via tf32 mma.sync, fp16 epilogue ----------------

__device__ __forceinline__ uint32_t f2tf32(float f) {
    uint32_t u;
    asm("cvt.rna.tf32.f32 %0, %1;" : "=r"(u) : "f"(f));
    return u;
}

#define LDA 132  // padded row length (bank-conflict avoidance)

__global__ __launch_bounds__(256) void k_gemm(const float* __restrict__ x,
                                              const float* __restrict__ W) {
    __shared__ uint32_t As[16][LDA];   // As[k][m] = tf32(x[brow+m][k0+k])
    __shared__ uint32_t Bs[16][LDA];   // Bs[k][o] = tf32(W[o][k0+k])

    int tid  = threadIdx.x;
    int lane = tid & 31;
    int wid  = tid >> 5;
    int warp_m = wid & 3;      // 0..3 -> 32 rows each
    int warp_n = wid >> 2;     // 0..1 -> 64 cols each
    int g  = lane >> 2;        // groupID 0..7
    int t4 = lane & 3;         // thread-in-group 0..3
    int brow = blockIdx.x * 128;

    float c[2][8][4];
#pragma unroll
    for (int mt = 0; mt < 2; mt++)
#pragma unroll
        for (int nt = 0; nt < 8; nt++)
#pragma unroll
            for (int r = 0; r < 4; r++) c[mt][nt][r] = 0.f;

    for (int k0 = 0; k0 < 128; k0 += 16) {
#pragma unroll
        for (int it = 0; it < 2; it++) {
            int idx = tid + it * 256;        // 0..511
            int m  = idx >> 2;               // 0..127
            int kq = (idx & 3) << 2;         // 0,4,8,12
            int grow = brow + m;
            float4 v = make_float4(0.f, 0.f, 0.f, 0.f);
            if (grow < MROWS)
                v = *(const float4*)(x + (size_t)grow * 128 + k0 + kq);
            As[kq + 0][m] = f2tf32(v.x);
            As[kq + 1][m] = f2tf32(v.y);
            As[kq + 2][m] = f2tf32(v.z);
            As[kq + 3][m] = f2tf32(v.w);
            float4 w = *(const float4*)(W + (size_t)m * 128 + k0 + kq);
            Bs[kq + 0][m] = f2tf32(w.x);
            Bs[kq + 1][m] = f2tf32(w.y);
            Bs[kq + 2][m] = f2tf32(w.z);
            Bs[kq + 3][m] = f2tf32(w.w);
        }
        __syncthreads();

#pragma unroll
        for (int ks = 0; ks < 2; ks++) {
            int kb = ks * 8;
            uint32_t a[2][4];
#pragma unroll
            for (int mt = 0; mt < 2; mt++) {
                int row = warp_m * 32 + mt * 16;
                a[mt][0] = As[kb + t4][row + g];
                a[mt][1] = As[kb + t4][row + g + 8];
                a[mt][2] = As[kb + t4 + 4][row + g];
                a[mt][3] = As[kb + t4 + 4][row + g + 8];
            }
            uint32_t b[8][2];
#pragma unroll
            for (int nt = 0; nt < 8; nt++) {
                int col = warp_n * 64 + nt * 8;
                b[nt][0] = Bs[kb + t4][col + g];
                b[nt][1] = Bs[kb + t4 + 4][col + g];
            }
#pragma unroll
            for (int mt = 0; mt < 2; mt++)
#pragma unroll
                for (int nt = 0; nt < 8; nt++) {
                    asm volatile(
                        "mma.sync.aligned.m16n8k8.row.col.f32.tf32.tf32.f32 "
                        "{%0,%1,%2,%3}, {%4,%5,%6,%7}, {%8,%9}, {%0,%1,%2,%3};"
                        : "+f"(c[mt][nt][0]), "+f"(c[mt][nt][1]),
                          "+f"(c[mt][nt][2]), "+f"(c[mt][nt][3])
                        : "r"(a[mt][0]), "r"(a[mt][1]), "r"(a[mt][2]), "r"(a[mt][3]),
                          "r"(b[nt][0]), "r"(b[nt][1]));
                }
        }
        __syncthreads();
    }

    // epilogue: frag rows (g, g+8), cols (2*t4, 2*t4+1) -> half2 stores
#pragma unroll
    for (int mt = 0; mt < 2; mt++) {
        int row0 = brow + warp_m * 32 + mt * 16 + g;
        int row1 = row0 + 8;
#pragma unroll
        for (int nt = 0; nt < 8; nt++) {
            int col = warp_n * 64 + nt * 8 + t4 * 2;
            if (row0 < MROWS)
                *(__half2*)(g_h + (size_t)row0 * 128 + col) =
                    __floats2half2_rn(c[mt][nt][0], c[mt][nt][1]);
            if (row1 < MROWS)
                *(__half2*)(g_h + (size_t)row1 * 128 + col) =
                    __floats2half2_rn(c[mt][nt][2], c[mt][nt][3]);
        }
    }
}

// ---------------- SpMM gather (fp16 h, fp32 accumulate) ----------------
// One 128-thread block per node. Thread layout: tid>>6 selects batch pair
// (0,1) or (2,3); tid&63 selects a feature pair (half2). fp32 accumulators.

__global__ __launch_bounds__(128) void k_spmm(float* __restrict__ out) {
    int n   = blockIdx.x;
    int tid = threadIdx.x;
    int hb  = tid >> 6;            // 0 -> batches 0,1 ; 1 -> batches 2,3
    int fo  = tid & 63;            // half2 index within row (features 2fo, 2fo+1)
    int b0  = hb * 2, b1 = b0 + 1;
    int s = g_rowptr[n];
    int e = g_rowptr[n + 1];

    const __half2* hp0 = (const __half2*)g_h + (size_t)b0 * NN * 64 + fo;
    const __half2* hp1 = (const __half2*)g_h + (size_t)b1 * NN * 64 + fo;

    float2 acc0 = make_float2(0.f, 0.f);
    float2 acc1 = make_float2(0.f, 0.f);

    int i = s;
    for (; i + 3 < e; i += 4) {
        int   c0 = g_col[i],     c1 = g_col[i + 1];
        int   c2 = g_col[i + 2], c3 = g_col[i + 3];
        float v0 = g_val[i],     v1 = g_val[i + 1];
        float v2 = g_val[i + 2], v3 = g_val[i + 3];
        float2 a0 = __half22float2(hp0[(size_t)c0 * 64]);
        float2 a1 = __half22float2(hp0[(size_t)c1 * 64]);
        float2 a2 = __half22float2(hp0[(size_t)c2 * 64]);
        float2 a3 = __half22float2(hp0[(size_t)c3 * 64]);
        float2 d0 = __half22float2(hp1[(size_t)c0 * 64]);
        float2 d1 = __half22float2(hp1[(size_t)c1 * 64]);
        float2 d2 = __half22float2(hp1[(size_t)c2 * 64]);
        float2 d3 = __half22float2(hp1[(size_t)c3 * 64]);
        acc0.x = fmaf(v0, a0.x, acc0.x); acc0.y = fmaf(v0, a0.y, acc0.y);
        acc0.x = fmaf(v1, a1.x, acc0.x); acc0.y = fmaf(v1, a1.y, acc0.y);
        acc0.x = fmaf(v2, a2.x, acc0.x); acc0.y = fmaf(v2, a2.y, acc0.y);
        acc0.x = fmaf(v3, a3.x, acc0.x); acc0.y = fmaf(v3, a3.y, acc0.y);
        acc1.x = fmaf(v0, d0.x, acc1.x); acc1.y = fmaf(v0, d0.y, acc1.y);
        acc1.x = fmaf(v1, d1.x, acc1.x); acc1.y = fmaf(v1, d1.y, acc1.y);
        acc1.x = fmaf(v2, d2.x, acc1.x); acc1.y = fmaf(v2, d2.y, acc1.y);
        acc1.x = fmaf(v3, d3.x, acc1.x); acc1.y = fmaf(v3, d3.y, acc1.y);
    }
    for (; i < e; i++) {
        int   ca = g_col[i];
        float va = g_val[i];
        float2 a = __half22float2(hp0[(size_t)ca * 64]);
        float2 d = __half22float2(hp1[(size_t)ca * 64]);
        acc0.x = fmaf(va, a.x, acc0.x); acc0.y = fmaf(va, a.y, acc0.y);
        acc1.x = fmaf(va, d.x, acc1.x); acc1.y = fmaf(va, d.y, acc1.y);
    }

    *(float2*)(out + ((size_t)b0 * NN + n) * FF + fo * 2) = acc0;
    *(float2*)(out + ((size_t)b1 * NN + n) * FF + fo * 2) = acc1;
}

// ---------------- launch ----------------

extern "C" void kernel_launch(void* const* d_in, const int* in_sizes, int n_in,
                              void* d_out, int out_size) {
    const float* x  = (const float*)d_in[0];   // [B,N,F_in]
    const float* W  = (const float*)d_in[1];   // [F_out,F_in]
    const int*   er = (const int*)d_in[2];     // [E] int32
    const int*   ec = (const int*)d_in[3];     // [E] int32
    const float* ev = (const float*)d_in[4];   // [E]
    float* out = (float*)d_out;
    int E = in_sizes[2];

    // Fork: CSR build on side stream s1, GEMM on main stream.
    cudaEventRecord(g_ev_root, 0);
    cudaStreamWaitEvent(g_s1, g_ev_root, 0);

    // CSR build (stream s1)
    k_zero_deg<<<(NN + 255) / 256, 256, 0, g_s1>>>();
    k_hist<<<(E + 255) / 256, 256, 0, g_s1>>>(er, E);
    k_scan1<<<NCHUNK, 256, 0, g_s1>>>();
    k_scan2<<<1, 256, 0, g_s1>>>();
    k_scan3<<<NCHUNK, 256, 0, g_s1>>>(E);
    k_scatter<<<(E + 255) / 256, 256, 0, g_s1>>>(er, ec, ev, E);
    cudaEventRecord(g_ev_csr, g_s1);

    // dense projection (tf32 tensor cores, fp16 output, main stream)
    k_gemm<<<(MROWS + 127) / 128, 256>>>(x, W);

    // join: SpMM needs both g_h (GEMM) and CSR arrays
    cudaStreamWaitEvent(0, g_ev_csr, 0);
    k_spmm<<<NN, 128>>>(out);
}

// round 8
// speedup vs baseline: 2.2419x; 1.0405x over previous
#include <cuda_runtime.h>
#include <cuda_fp16.h>
#include <stdint.h>

#define BB 4
#define NN 50000
#define FF 128
#define EE 800000
#define MROWS (BB * NN)                 // 200000 projected rows
#define NCHUNK ((NN + 255) / 256)       // 196 scan chunks

// ---- device scratch ----
__device__ __half g_h[(size_t)MROWS * FF];  // projected features, fp16, 51.2 MB
__device__ int   g_deg[NN];
__device__ int   g_excl[NN];
__device__ int   g_blksum[NCHUNK];
__device__ int   g_blkoff[NCHUNK];
__device__ int   g_rowptr[NN + 1];
__device__ int   g_cursor[NN];
__device__ int2  g_cv[EE];                  // packed (col, val-bits)

// ---- streams/events for capture forking ----
static cudaStream_t g_s1;
static cudaEvent_t  g_ev_root, g_ev_csr;
struct _StreamInit {
    _StreamInit() {
        cudaStreamCreateWithFlags(&g_s1, cudaStreamNonBlocking);
        cudaEventCreateWithFlags(&g_ev_root, cudaEventDisableTiming);
        cudaEventCreateWithFlags(&g_ev_csr,  cudaEventDisableTiming);
    }
};
static _StreamInit g_stream_init;

// ---------------- CSR build ----------------

__global__ void k_zero_deg() {
    int i = blockIdx.x * 256 + threadIdx.x;
    if (i < NN) g_deg[i] = 0;
}

__global__ void k_hist(const int* __restrict__ er, int E) {
    int e = blockIdx.x * 256 + threadIdx.x;
    if (e < E) atomicAdd(&g_deg[er[e]], 1);
}

__global__ void k_scan1() {
    __shared__ int s[256];
    int b = blockIdx.x, t = threadIdx.x;
    int i = b * 256 + t;
    int v = (i < NN) ? g_deg[i] : 0;
    s[t] = v;
    __syncthreads();
#pragma unroll
    for (int o = 1; o < 256; o <<= 1) {
        int x = (t >= o) ? s[t - o] : 0;
        __syncthreads();
        s[t] += x;
        __syncthreads();
    }
    if (i < NN) g_excl[i] = s[t] - v;
    if (t == 255) g_blksum[b] = s[255];
}

__global__ void k_scan2() {
    __shared__ int s[256];
    int t = threadIdx.x;
    int v = (t < NCHUNK) ? g_blksum[t] : 0;
    s[t] = v;
    __syncthreads();
#pragma unroll
    for (int o = 1; o < 256; o <<= 1) {
        int x = (t >= o) ? s[t - o] : 0;
        __syncthreads();
        s[t] += x;
        __syncthreads();
    }
    if (t < NCHUNK) g_blkoff[t] = s[t] - v;
}

__global__ void k_scan3(int E) {
    int b = blockIdx.x, t = threadIdx.x;
    int i = b * 256 + t;
    if (i < NN) {
        int p = g_excl[i] + g_blkoff[b];
        g_rowptr[i] = p;
        g_cursor[i] = p;
    }
    if (i == 0) g_rowptr[NN] = E;
}

__global__ void k_scatter(const int* __restrict__ er,
                          const int* __restrict__ ec,
                          const float* __restrict__ ev, int E) {
    int e = blockIdx.x * 256 + threadIdx.x;
    if (e < E) {
        int r = er[e];
        int p = atomicAdd(&g_cursor[r], 1);
        g_cv[p] = make_int2(ec[e], __float_as_int(ev[e]));
    }
}

// ---------------- GEMM: h = x @ W^T, tf32 mma.sync, double-buffered ----------------
// BM=128, BN=128, BK=16, 256 threads = 8 warps (4m x 2n), 32x64 warp tile.

__device__ __forceinline__ uint32_t f2tf32(float f) {
    uint32_t u;
    asm("cvt.rna.tf32.f32 %0, %1;" : "=r"(u) : "f"(f));
    return u;
}

#define LDA 132  // padded row length (bank-conflict avoidance)

__global__ __launch_bounds__(256) void k_gemm(const float* __restrict__ x,
                                              const float* __restrict__ W) {
    __shared__ uint32_t As[2][16][LDA];   // As[buf][k][m]
    __shared__ uint32_t Bs[2][16][LDA];   // Bs[buf][k][o]

    int tid  = threadIdx.x;
    int lane = tid & 31;
    int wid  = tid >> 5;
    int warp_m = wid & 3;
    int warp_n = wid >> 2;
    int g  = lane >> 2;
    int t4 = lane & 3;
    int brow = blockIdx.x * 128;

    // per-thread load slots: 2 float4 per operand per tile
    int m0  = tid >> 1;                 // 0..127
    int kq0 = (tid & 1) << 3;           // 0 or 8 -> covers k 0..7 / 8..15 via two float4
    // thread loads x[m0][k0+kq0 .. +7] (2 float4) and W[m0][k0+kq0 .. +7]

    float c[2][8][4];
#pragma unroll
    for (int mt = 0; mt < 2; mt++)
#pragma unroll
        for (int nt = 0; nt < 8; nt++)
#pragma unroll
            for (int r = 0; r < 4; r++) c[mt][nt][r] = 0.f;

    int grow = brow + m0;
    bool rok = (grow < MROWS);
    const float* xrow = x + (size_t)grow * 128;
    const float* wrow = W + (size_t)m0 * 128;

    float4 xa, xb, wa, wb;
    // prologue: load k0=0 tile
    xa = rok ? *(const float4*)(xrow + kq0)     : make_float4(0, 0, 0, 0);
    xb = rok ? *(const float4*)(xrow + kq0 + 4) : make_float4(0, 0, 0, 0);
    wa = *(const float4*)(wrow + kq0);
    wb = *(const float4*)(wrow + kq0 + 4);
    {
        As[0][kq0 + 0][m0] = f2tf32(xa.x); As[0][kq0 + 1][m0] = f2tf32(xa.y);
        As[0][kq0 + 2][m0] = f2tf32(xa.z); As[0][kq0 + 3][m0] = f2tf32(xa.w);
        As[0][kq0 + 4][m0] = f2tf32(xb.x); As[0][kq0 + 5][m0] = f2tf32(xb.y);
        As[0][kq0 + 6][m0] = f2tf32(xb.z); As[0][kq0 + 7][m0] = f2tf32(xb.w);
        Bs[0][kq0 + 0][m0] = f2tf32(wa.x); Bs[0][kq0 + 1][m0] = f2tf32(wa.y);
        Bs[0][kq0 + 2][m0] = f2tf32(wa.z); Bs[0][kq0 + 3][m0] = f2tf32(wa.w);
        Bs[0][kq0 + 4][m0] = f2tf32(wb.x); Bs[0][kq0 + 5][m0] = f2tf32(wb.y);
        Bs[0][kq0 + 6][m0] = f2tf32(wb.z); Bs[0][kq0 + 7][m0] = f2tf32(wb.w);
    }
    __syncthreads();

#pragma unroll
    for (int kt = 0; kt < 8; kt++) {
        int cur = kt & 1;
        // issue next tile's global loads early (overlap with mma)
        if (kt < 7) {
            int kn = (kt + 1) * 16;
            xa = rok ? *(const float4*)(xrow + kn + kq0)     : make_float4(0, 0, 0, 0);
            xb = rok ? *(const float4*)(xrow + kn + kq0 + 4) : make_float4(0, 0, 0, 0);
            wa = *(const float4*)(wrow + kn + kq0);
            wb = *(const float4*)(wrow + kn + kq0 + 4);
        }

        // compute current tile
#pragma unroll
        for (int ks = 0; ks < 2; ks++) {
            int kb = ks * 8;
            uint32_t a[2][4];
#pragma unroll
            for (int mt = 0; mt < 2; mt++) {
                int row = warp_m * 32 + mt * 16;
                a[mt][0] = As[cur][kb + t4][row + g];
                a[mt][1] = As[cur][kb + t4][row + g + 8];
                a[mt][2] = As[cur][kb + t4 + 4][row + g];
                a[mt][3] = As[cur][kb + t4 + 4][row + g + 8];
            }
            uint32_t b[8][2];
#pragma unroll
            for (int nt = 0; nt < 8; nt++) {
                int col = warp_n * 64 + nt * 8;
                b[nt][0] = Bs[cur][kb + t4][col + g];
                b[nt][1] = Bs[cur][kb + t4 + 4][col + g];
            }
#pragma unroll
            for (int mt = 0; mt < 2; mt++)
#pragma unroll
                for (int nt = 0; nt < 8; nt++) {
                    asm volatile(
                        "mma.sync.aligned.m16n8k8.row.col.f32.tf32.tf32.f32 "
                        "{%0,%1,%2,%3}, {%4,%5,%6,%7}, {%8,%9}, {%0,%1,%2,%3};"
                        : "+f"(c[mt][nt][0]), "+f"(c[mt][nt][1]),
                          "+f"(c[mt][nt][2]), "+f"(c[mt][nt][3])
                        : "r"(a[mt][0]), "r"(a[mt][1]), "r"(a[mt][2]), "r"(a[mt][3]),
                          "r"(b[nt][0]), "r"(b[nt][1]));
                }
        }

        if (kt < 7) {
            int nxt = cur ^ 1;
            As[nxt][kq0 + 0][m0] = f2tf32(xa.x); As[nxt][kq0 + 1][m0] = f2tf32(xa.y);
            As[nxt][kq0 + 2][m0] = f2tf32(xa.z); As[nxt][kq0 + 3][m0] = f2tf32(xa.w);
            As[nxt][kq0 + 4][m0] = f2tf32(xb.x); As[nxt][kq0 + 5][m0] = f2tf32(xb.y);
            As[nxt][kq0 + 6][m0] = f2tf32(xb.z); As[nxt][kq0 + 7][m0] = f2tf32(xb.w);
            Bs[nxt][kq0 + 0][m0] = f2tf32(wa.x); Bs[nxt][kq0 + 1][m0] = f2tf32(wa.y);
            Bs[nxt][kq0 + 2][m0] = f2tf32(wa.z); Bs[nxt][kq0 + 3][m0] = f2tf32(wa.w);
            Bs[nxt][kq0 + 4][m0] = f2tf32(wb.x); Bs[nxt][kq0 + 5][m0] = f2tf32(wb.y);
            Bs[nxt][kq0 + 6][m0] = f2tf32(wb.z); Bs[nxt][kq0 + 7][m0] = f2tf32(wb.w);
            __syncthreads();
        }
    }

    // epilogue: frag rows (g, g+8), cols (2*t4, 2*t4+1) -> half2 stores
#pragma unroll
    for (int mt = 0; mt < 2; mt++) {
        int row0 = brow + warp_m * 32 + mt * 16 + g;
        int row1 = row0 + 8;
#pragma unroll
        for (int nt = 0; nt < 8; nt++) {
            int col = warp_n * 64 + nt * 8 + t4 * 2;
            if (row0 < MROWS)
                *(__half2*)(g_h + (size_t)row0 * 128 + col) =
                    __floats2half2_rn(c[mt][nt][0], c[mt][nt][1]);
            if (row1 < MROWS)
                *(__half2*)(g_h + (size_t)row1 * 128 + col) =
                    __floats2half2_rn(c[mt][nt][2], c[mt][nt][3]);
        }
    }
}

// ---------------- SpMM gather (fp16 h, fp32 accumulate) ----------------
// One 128-thread block per node; tid>>6 selects batch pair; tid&63 = half2 slot.

__global__ __launch_bounds__(128) void k_spmm(float* __restrict__ out) {
    int n   = blockIdx.x;
    int tid = threadIdx.x;
    int hb  = tid >> 6;
    int fo  = tid & 63;
    int b0  = hb * 2, b1 = b0 + 1;
    int s = g_rowptr[n];
    int e = g_rowptr[n + 1];

    const __half2* hp0 = (const __half2*)g_h + (size_t)b0 * NN * 64 + fo;
    const __half2* hp1 = (const __half2*)g_h + (size_t)b1 * NN * 64 + fo;

    float2 acc0 = make_float2(0.f, 0.f);
    float2 acc1 = make_float2(0.f, 0.f);

    int i = s;
    for (; i + 3 < e; i += 4) {
        int2 cv0 = __ldg(&g_cv[i]),     cv1 = __ldg(&g_cv[i + 1]);
        int2 cv2 = __ldg(&g_cv[i + 2]), cv3 = __ldg(&g_cv[i + 3]);
        float v0 = __int_as_float(cv0.y), v1 = __int_as_float(cv1.y);
        float v2 = __int_as_float(cv2.y), v3 = __int_as_float(cv3.y);
        float2 a0 = __half22float2(__ldg(hp0 + (size_t)cv0.x * 64));
        float2 a1 = __half22float2(__ldg(hp0 + (size_t)cv1.x * 64));
        float2 a2 = __half22float2(__ldg(hp0 + (size_t)cv2.x * 64));
        float2 a3 = __half22float2(__ldg(hp0 + (size_t)cv3.x * 64));
        float2 d0 = __half22float2(__ldg(hp1 + (size_t)cv0.x * 64));
        float2 d1 = __half22float2(__ldg(hp1 + (size_t)cv1.x * 64));
        float2 d2 = __half22float2(__ldg(hp1 + (size_t)cv2.x * 64));
        float2 d3 = __half22float2(__ldg(hp1 + (size_t)cv3.x * 64));
        acc0.x = fmaf(v0, a0.x, acc0.x); acc0.y = fmaf(v0, a0.y, acc0.y);
        acc0.x = fmaf(v1, a1.x, acc0.x); acc0.y = fmaf(v1, a1.y, acc0.y);
        acc0.x = fmaf(v2, a2.x, acc0.x); acc0.y = fmaf(v2, a2.y, acc0.y);
        acc0.x = fmaf(v3, a3.x, acc0.x); acc0.y = fmaf(v3, a3.y, acc0.y);
        acc1.x = fmaf(v0, d0.x, acc1.x); acc1.y = fmaf(v0, d0.y, acc1.y);
        acc1.x = fmaf(v1, d1.x, acc1.x); acc1.y = fmaf(v1, d1.y, acc1.y);
        acc1.x = fmaf(v2, d2.x, acc1.x); acc1.y = fmaf(v2, d2.y, acc1.y);
        acc1.x = fmaf(v3, d3.x, acc1.x); acc1.y = fmaf(v3, d3.y, acc1.y);
    }
    for (; i < e; i++) {
        int2 cv = __ldg(&g_cv[i]);
        float va = __int_as_float(cv.y);
        float2 a = __half22float2(__ldg(hp0 + (size_t)cv.x * 64));
        float2 d = __half22float2(__ldg(hp1 + (size_t)cv.x * 64));
        acc0.x = fmaf(va, a.x, acc0.x); acc0.y = fmaf(va, a.y, acc0.y);
        acc1.x = fmaf(va, d.x, acc1.x); acc1.y = fmaf(va, d.y, acc1.y);
    }

    *(float2*)(out + ((size_t)b0 * NN + n) * FF + fo * 2) = acc0;
    *(float2*)(out + ((size_t)b1 * NN + n) * FF + fo * 2) = acc1;
}

// ---------------- launch ----------------

extern "C" void kernel_launch(void* const* d_in, const int* in_sizes, int n_in,
                              void* d_out, int out_size) {
    const float* x  = (const float*)d_in[0];   // [B,N,F_in]
    const float* W  = (const float*)d_in[1];   // [F_out,F_in]
    const int*   er = (const int*)d_in[2];     // [E] int32
    const int*   ec = (const int*)d_in[3];     // [E] int32
    const float* ev = (const float*)d_in[4];   // [E]
    float* out = (float*)d_out;
    int E = in_sizes[2];

    // Fork: CSR build on side stream s1, GEMM on main stream.
    cudaEventRecord(g_ev_root, 0);
    cudaStreamWaitEvent(g_s1, g_ev_root, 0);

    // CSR build (stream s1)
    k_zero_deg<<<(NN + 255) / 256, 256, 0, g_s1>>>();
    k_hist<<<(E + 255) / 256, 256, 0, g_s1>>>(er, E);
    k_scan1<<<NCHUNK, 256, 0, g_s1>>>();
    k_scan2<<<1, 256, 0, g_s1>>>();
    k_scan3<<<NCHUNK, 256, 0, g_s1>>>(E);
    k_scatter<<<(E + 255) / 256, 256, 0, g_s1>>>(er, ec, ev, E);
    cudaEventRecord(g_ev_csr, g_s1);

    // dense projection (tf32 tensor cores, double-buffered, fp16 output)
    k_gemm<<<(MROWS + 127) / 128, 256>>>(x, W);

    // join: SpMM needs both g_h (GEMM) and CSR arrays
    cudaStreamWaitEvent(0, g_ev_csr, 0);
    k_spmm<<<NN, 128>>>(out);
}